// round 4
// baseline (speedup 1.0000x reference)
#include <cuda_runtime.h>
#include <math.h>

#define N 16384
#define B 16384
#define THREADS 256
#define BLOCKS (N / THREADS)      // 64
#define SCAN_ITEMS (B / THREADS)  // 64 buckets per thread in the centralized scans

// ---------------- static device scratch (no allocation allowed) ----------------
__device__ int    g_count[B];     // items per bucket (final value after hist)
__device__ int    g_start[B];     // exclusive prefix of counts
__device__ float  g_bsum[B];      // sum of exp(theta) per bucket
__device__ float  g_bsuffix[B];   // exclusive suffix: sum over buckets > b
__device__ float2 g_sorted[N];    // (time, exp(theta)) bucket-grouped
__device__ float  g_acc[2];       // [0]=sum ev*(theta-logS), [1]=sum ev
__device__ int    g_done;         // last-block-done counter for final write

// grid barrier state (generation counter survives across replays; harmless)
__device__ int          g_bar_count = 0;
__device__ volatile int g_bar_gen   = 0;

__device__ __forceinline__ void grid_barrier() {
    __threadfence();                 // every thread publishes its writes
    __syncthreads();
    if (threadIdx.x == 0) {
        int gen = g_bar_gen;
        if (atomicAdd(&g_bar_count, 1) == (int)gridDim.x - 1) {
            g_bar_count = 0;         // safe: nobody re-arrives until release
            __threadfence();
            g_bar_gen = gen + 1;     // release
        } else {
            while (g_bar_gen == gen) __nanosleep(32);
        }
    }
    __syncthreads();
}

__device__ __forceinline__ int bucket_of(float t) {
    int b = (int)(t * 16384.0f);     // *2^14 is exact & monotone in fp32
    b = b < 0 ? 0 : b;
    return b > (B - 1) ? (B - 1) : b;
}

__global__ void __launch_bounds__(THREADS)
cox_fused(const float* __restrict__ risk,
          const float* __restrict__ time_,
          const float* __restrict__ event_,
          float* __restrict__ out) {
    __shared__ int   s_i[8];
    __shared__ float s_f[8];
    __shared__ float s_num[8];
    __shared__ float s_den[8];

    const int tid  = threadIdx.x;
    const int lane = tid & 31;
    const int warp = tid >> 5;
    const int gid  = blockIdx.x * THREADS + tid;

    // ---- phase 0: init (each thread owns one bucket slot) ----
    __stcg(&g_count[gid], 0);
    __stcg(&g_bsum[gid], 0.0f);
    if (gid == 0) { g_acc[0] = 0.0f; g_acc[1] = 0.0f; g_done = 0; }

    // element data lives in registers for the whole kernel
    const float t  = time_[gid];
    const float th = risk[gid];
    const float ev = event_[gid];
    const float e  = expf(th);
    const int   b  = bucket_of(t);

    grid_barrier();   // zeros visible before atomics

    // ---- phase 1: histogram; rank = within-bucket slot (free scatter index) ----
    const int rank = atomicAdd(&g_count[b], 1);
    atomicAdd(&g_bsum[b], e);

    grid_barrier();   // counts/bsums final

    // ---- phase 2: scans (blocks 0 and 1 in parallel; others wait) ----
    if (blockIdx.x == 0) {
        // exclusive prefix of counts -> g_start
        const int base = tid * SCAN_ITEMS;
        int run = 0;
        #pragma unroll 8
        for (int i = 0; i < SCAN_ITEMS; ++i) {
            __stcg(&g_start[base + i], run);          // local-exclusive
            run += __ldcg(&g_count[base + i]);
        }
        int v = run;                                   // inclusive warp scan of chunk totals
        #pragma unroll
        for (int d = 1; d < 32; d <<= 1) {
            int n = __shfl_up_sync(0xffffffffu, v, d);
            if (lane >= d) v += n;
        }
        if (lane == 31) s_i[warp] = v;
        __syncthreads();
        if (warp == 0) {
            int w = (lane < 8) ? s_i[lane] : 0;
            #pragma unroll
            for (int d = 1; d < 8; d <<= 1) {
                int n = __shfl_up_sync(0xffffffffu, w, d);
                if (lane >= d) w += n;
            }
            if (lane < 8) s_i[lane] = w;
        }
        __syncthreads();
        const int excl = ((warp == 0) ? 0 : s_i[warp - 1]) + (v - run);
        #pragma unroll 8
        for (int i = 0; i < SCAN_ITEMS; ++i)
            __stcg(&g_start[base + i], __ldcg(&g_start[base + i]) + excl);
    } else if (blockIdx.x == 1) {
        // exclusive suffix of bsum -> g_bsuffix (direct reversed scan)
        const int base = tid * SCAN_ITEMS;
        float run = 0.0f;
        #pragma unroll 8
        for (int i = 0; i < SCAN_ITEMS; ++i) {
            const int bb = B - 1 - (base + i);
            __stcg(&g_bsuffix[bb], run);
            run += __ldcg(&g_bsum[bb]);
        }
        float v = run;
        #pragma unroll
        for (int d = 1; d < 32; d <<= 1) {
            float n = __shfl_up_sync(0xffffffffu, v, d);
            if (lane >= d) v += n;
        }
        if (lane == 31) s_f[warp] = v;
        __syncthreads();
        if (warp == 0) {
            float w = (lane < 8) ? s_f[lane] : 0.0f;
            #pragma unroll
            for (int d = 1; d < 8; d <<= 1) {
                float n = __shfl_up_sync(0xffffffffu, w, d);
                if (lane >= d) w += n;
            }
            if (lane < 8) s_f[lane] = w;
        }
        __syncthreads();
        const float excl = ((warp == 0) ? 0.0f : s_f[warp - 1]) + (v - run);
        #pragma unroll 8
        for (int i = 0; i < SCAN_ITEMS; ++i) {
            const int bb = B - 1 - (base + i);
            __stcg(&g_bsuffix[bb], __ldcg(&g_bsuffix[bb]) + excl);
        }
    }

    grid_barrier();   // start/suffix final

    // ---- phase 3: scatter (no atomics: start + rank) ----
    const int myStart = __ldcg(&g_start[b]);
    __stcg(&g_sorted[myStart + rank], make_float2(t, e));

    grid_barrier();   // sorted array complete

    // ---- phase 4: per-sample loss + reduce ----
    float S = __ldcg(&g_bsuffix[b]);                  // buckets strictly above b
    const int en = myStart + __ldcg(&g_count[b]);
    for (int p = myStart; p < en; ++p) {              // exact in-bucket filter (avg 1 iter)
        float2 v2 = __ldcg(&g_sorted[p]);
        if (v2.x >= t) S += v2.y;
    }
    float num = ev * (th - logf(S));
    float den = ev;

    #pragma unroll
    for (int d = 16; d > 0; d >>= 1) {
        num += __shfl_down_sync(0xffffffffu, num, d);
        den += __shfl_down_sync(0xffffffffu, den, d);
    }
    if (lane == 0) { s_num[warp] = num; s_den[warp] = den; }
    __syncthreads();
    if (warp == 0) {
        num = (lane < 8) ? s_num[lane] : 0.0f;
        den = (lane < 8) ? s_den[lane] : 0.0f;
        #pragma unroll
        for (int d = 4; d > 0; d >>= 1) {
            num += __shfl_down_sync(0xffffffffu, num, d);
            den += __shfl_down_sync(0xffffffffu, den, d);
        }
        if (lane == 0) {
            atomicAdd(&g_acc[0], num);
            atomicAdd(&g_acc[1], den);
            __threadfence();
            // last block to finish writes the result (replaces barrier + final kernel)
            if (atomicAdd(&g_done, 1) == (int)gridDim.x - 1) {
                float a = atomicAdd(&g_acc[0], 0.0f);   // coherent read
                float d2 = atomicAdd(&g_acc[1], 0.0f);
                out[0] = -a / d2;
            }
        }
    }
}

extern "C" void kernel_launch(void* const* d_in, const int* in_sizes, int n_in,
                              void* d_out, int out_size) {
    const float* risk   = (const float*)d_in[0];
    const float* time_  = (const float*)d_in[1];
    const float* event_ = (const float*)d_in[2];
    float* out = (float*)d_out;

    cox_fused<<<BLOCKS, THREADS>>>(risk, time_, event_, out);
}